// round 1
// baseline (speedup 1.0000x reference)
#include <cuda_runtime.h>
#include <math.h>

#define NBOX 1024
#define EPSF 1e-8f
#define NMS_TH 0.1f
#define MAXP (1<<18)

struct Box {
    float cx, cy, hx, hy, cs, sn;
    float corx[4], cory[4];
    float rad, zmin, zmax, area, vol;
    float pad;
};

__device__ Box g_gt[NBOX];
__device__ Box g_pred[NBOX];
__device__ unsigned g_supp[NBOX * 32];      // suppression bitmask, sorted-order rows
__device__ int g_order[NBOX];               // sorted pos -> orig idx
__device__ int g_pos[NBOX];                 // orig idx -> sorted pos
__device__ int g_keep_orig[NBOX];           // keep flag per orig gt idx
__device__ int g_cnt_gg;
__device__ int g_cnt_pg;
__device__ unsigned g_pairs_gg[MAXP];
__device__ unsigned g_pairs_pg[MAXP];
__device__ unsigned long long g_rowbest[NBOX];

// ---------------------------------------------------------------------------
// Rotated-rectangle intersection area, replicating the reference algorithm:
// corners-in-box (with 1e-5 tol), 16 edge intersections, centroid, stable
// angle sort, shoelace. Candidate order matches the reference concatenation.
// ---------------------------------------------------------------------------
__device__ float inter_area(const Box& a, const Box& b) {
    float px[24], py[24];
    int k = 0;

    // corners of A inside B
#pragma unroll
    for (int q = 0; q < 4; q++) {
        float dxp = a.corx[q] - b.cx, dyp = a.cory[q] - b.cy;
        float lx =  dxp * b.cs + dyp * b.sn;
        float ly = -dxp * b.sn + dyp * b.cs;
        if (fabsf(lx) <= b.hx + 1e-5f && fabsf(ly) <= b.hy + 1e-5f) {
            px[k] = a.corx[q]; py[k] = a.cory[q]; k++;
        }
    }
    // corners of B inside A
#pragma unroll
    for (int q = 0; q < 4; q++) {
        float dxp = b.corx[q] - a.cx, dyp = b.cory[q] - a.cy;
        float lx =  dxp * a.cs + dyp * a.sn;
        float ly = -dxp * a.sn + dyp * a.cs;
        if (fabsf(lx) <= a.hx + 1e-5f && fabsf(ly) <= a.hy + 1e-5f) {
            px[k] = b.corx[q]; py[k] = b.cory[q]; k++;
        }
    }
    // edge-edge intersections, p-major q-minor order (matches reshape(16))
#pragma unroll
    for (int p = 0; p < 4; p++) {
        float a0x = a.corx[p], a0y = a.cory[p];
        float a1x = a.corx[(p + 1) & 3], a1y = a.cory[(p + 1) & 3];
        float d1x = a1x - a0x, d1y = a1y - a0y;
#pragma unroll
        for (int q = 0; q < 4; q++) {
            float b0x = b.corx[q], b0y = b.cory[q];
            float b1x = b.corx[(q + 1) & 3], b1y = b.cory[(q + 1) & 3];
            float d2x = b1x - b0x, d2y = b1y - b0y;
            float r0x = b0x - a0x, r0y = b0y - a0y;
            float den = d1x * d2y - d1y * d2x;
            if (fabsf(den) > EPSF) {
                float t = (r0x * d2y - r0y * d2x) / den;
                float u = (r0x * d1y - r0y * d1x) / den;
                if (t >= 0.f && t <= 1.f && u >= 0.f && u <= 1.f) {
                    px[k] = a0x + t * d1x;
                    py[k] = a0y + t * d1y;
                    k++;
                }
            }
        }
    }

    if (k < 3) return 0.f;

    float sx = 0.f, sy = 0.f;
    for (int i = 0; i < k; i++) { sx += px[i]; sy += py[i]; }
    float fk = (float)k;
    float cxm = sx / fk, cym = sy / fk;

    float ang[24];
    for (int i = 0; i < k; i++) {
        px[i] -= cxm; py[i] -= cym;
        ang[i] = atan2f(py[i], px[i]);
    }
    // stable insertion sort ascending by angle (matches stable jnp.argsort)
    for (int i = 1; i < k; i++) {
        float ax = px[i], ay = py[i], aa = ang[i];
        int j = i - 1;
        while (j >= 0 && ang[j] > aa) {
            px[j + 1] = px[j]; py[j + 1] = py[j]; ang[j + 1] = ang[j];
            j--;
        }
        px[j + 1] = ax; py[j + 1] = ay; ang[j + 1] = aa;
    }
    float s = 0.f;
    for (int i = 0; i < k; i++) {
        int j = (i + 1 == k) ? 0 : (i + 1);
        s += px[i] * py[j] - py[i] * px[j];
    }
    return 0.5f * fabsf(s);
}

// ---------------------------------------------------------------------------
__global__ void k_init(const float* __restrict__ labels,
                       const float* __restrict__ cls,
                       float* __restrict__ out) {
    int t = blockIdx.x * blockDim.x + threadIdx.x;
    if (t < NBOX * 32) g_supp[t] = 0u;
    if (t == 0) { g_cnt_gg = 0; g_cnt_pg = 0; }
    if (t < NBOX) {
        g_rowbest[t] = 0xFFFFFFFFull;  // (val=0.0f bits)<<32 | (~idx0)
        float lab = labels[t];
        float sgm = 1.0f / (1.0f + expf(-cls[t]));
        out[t] = (sgm > 0.55f && lab > 0.55f) ? 1.0f : 0.0f;
        out[NBOX + t] = lab;
    }
}

__global__ void k_prep(const float* __restrict__ pred_boxes,
                       const float* __restrict__ gt_boxes) {
    int t = blockIdx.x * blockDim.x + threadIdx.x;
    if (t >= 2 * NBOX) return;
    bool isgt = (t < NBOX);
    int i = isgt ? t : t - NBOX;
    const float* p = isgt ? (gt_boxes + i * 8) : (pred_boxes + i * 7);
    Box b;
    b.cx = p[0]; b.cy = p[1];
    float z = p[2], dx = p[3], dy = p[4], dz = p[5], r = p[6];
    b.hx = 0.5f * dx; b.hy = 0.5f * dy;
    float cs = cosf(r), sn = sinf(r);
    b.cs = cs; b.sn = sn;
    const float sxt[4] = {1.f, 1.f, -1.f, -1.f};
    const float syt[4] = {1.f, -1.f, -1.f, 1.f};
#pragma unroll
    for (int q = 0; q < 4; q++) {
        float lx = sxt[q] * b.hx, ly = syt[q] * b.hy;
        b.corx[q] = lx * cs - ly * sn + b.cx;
        b.cory[q] = lx * sn + ly * cs + b.cy;
    }
    b.rad = sqrtf(b.hx * b.hx + b.hy * b.hy) + 5e-4f;
    b.zmin = z - dz * 0.5f;
    b.zmax = z + dz * 0.5f;
    b.area = dx * dy;
    b.vol = dx * dy * dz;
    b.pad = 0.f;
    if (isgt) g_gt[i] = b; else g_pred[i] = b;
}

// stable descending sort by score (ties: ascending orig index), bitonic
__global__ void k_sort(const float* __restrict__ labels) {
    __shared__ unsigned long long key[NBOX];
    int t = threadIdx.x;
    unsigned u = __float_as_uint(labels[t]);
    u = (u & 0x80000000u) ? ~u : (u | 0x80000000u);   // order-preserving map
    key[t] = ((unsigned long long)(~u) << 32) | (unsigned)t;
    __syncthreads();
    for (int k2 = 2; k2 <= NBOX; k2 <<= 1) {
        for (int j = k2 >> 1; j > 0; j >>= 1) {
            int ixj = t ^ j;
            if (ixj > t) {
                unsigned long long A = key[t], B = key[ixj];
                bool up = ((t & k2) == 0);
                if ((A > B) == up) { key[t] = B; key[ixj] = A; }
            }
            __syncthreads();
        }
    }
    int orig = (int)(unsigned)(key[t] & 0xFFFFFFFFull);
    g_order[t] = orig;
    g_pos[orig] = t;
}

__global__ void k_prune_gg() {
    int i = blockIdx.y;
    int j = blockIdx.x * blockDim.x + threadIdx.x;
    if (j >= NBOX || j <= i) return;
    float dx = g_gt[i].cx - g_gt[j].cx;
    float dy = g_gt[i].cy - g_gt[j].cy;
    float rr = g_gt[i].rad + g_gt[j].rad;
    if (dx * dx + dy * dy <= rr * rr) {
        int idx = atomicAdd(&g_cnt_gg, 1);
        if (idx < MAXP) g_pairs_gg[idx] = ((unsigned)i << 10) | (unsigned)j;
    }
}

__global__ void k_heavy_gg() {
    int n = g_cnt_gg; if (n > MAXP) n = MAXP;
    for (int idx = blockIdx.x * blockDim.x + threadIdx.x; idx < n;
         idx += gridDim.x * blockDim.x) {
        unsigned pr = g_pairs_gg[idx];
        int i = pr >> 10, j = pr & 1023;
        float inter = inter_area(g_gt[i], g_gt[j]);
        float iou = inter / fmaxf(g_gt[i].area + g_gt[j].area - inter, EPSF);
        if (iou > NMS_TH) {
            int a = g_pos[i], b = g_pos[j];
            int lo = min(a, b), hi = max(a, b);
            atomicOr(&g_supp[lo * 32 + (hi >> 5)], 1u << (hi & 31));
        }
    }
}

// single-warp sequential greedy NMS scan over the suppression bitmask.
// keep mask lives in registers (lane w owns word w). The "diagonal word"
// g_supp[i*32 + i/32] is tracked redundantly on all lanes so the per-
// iteration keep-bit test needs no shfl.
__global__ void k_nms() {
    unsigned lane = threadIdx.x;   // 32 threads
    unsigned keep = 0xFFFFFFFFu;
    for (int w = 0; w < 32; w++) {
        unsigned kcur = __shfl_sync(0xFFFFFFFFu, keep, w);
        unsigned mrow[32], mdia[32];
#pragma unroll
        for (int u = 0; u < 32; u++) {
            int i = w * 32 + u;
            mrow[u] = g_supp[i * 32 + lane];
            mdia[u] = g_supp[i * 32 + w];
        }
#pragma unroll
        for (int u = 0; u < 32; u++) {
            if ((kcur >> u) & 1u) {
                unsigned lowmask = (2u << u) - 1u;   // bits 0..u (u=31 -> all)
                unsigned m = mrow[u];
                m = (lane < (unsigned)w) ? 0u
                    : ((lane == (unsigned)w) ? (m & ~lowmask) : m);
                keep &= ~m;
                kcur &= ~(mdia[u] & ~lowmask);
            }
        }
    }
    // scatter keep back to original indices
#pragma unroll
    for (int b = 0; b < 32; b++) {
        int a = (int)lane * 32 + b;
        int orig = g_order[a];
        g_keep_orig[orig] = (int)((keep >> b) & 1u);
    }
}

__global__ void k_prune_pg() {
    int i = blockIdx.y;                                   // pred row
    int j = blockIdx.x * blockDim.x + threadIdx.x;        // gt col
    if (j >= NBOX) return;
    if (!g_keep_orig[j]) return;                          // suppressed -> iou 0
    const Box& a = g_pred[i];
    const Box& b = g_gt[j];
    float oh = fminf(a.zmax, b.zmax) - fmaxf(a.zmin, b.zmin);
    if (oh <= 0.f) return;                                // inter3d exactly 0
    float dx = a.cx - b.cx, dy = a.cy - b.cy;
    float rr = a.rad + b.rad;
    if (dx * dx + dy * dy <= rr * rr) {
        int idx = atomicAdd(&g_cnt_pg, 1);
        if (idx < MAXP) g_pairs_pg[idx] = ((unsigned)i << 10) | (unsigned)j;
    }
}

__global__ void k_heavy_pg() {
    int n = g_cnt_pg; if (n > MAXP) n = MAXP;
    for (int idx = blockIdx.x * blockDim.x + threadIdx.x; idx < n;
         idx += gridDim.x * blockDim.x) {
        unsigned pr = g_pairs_pg[idx];
        int i = pr >> 10, j = pr & 1023;
        const Box& a = g_pred[i];
        const Box& b = g_gt[j];
        float inter = inter_area(a, b);
        float oh = fmaxf(fminf(a.zmax, b.zmax) - fmaxf(a.zmin, b.zmin), 0.f);
        float i3 = inter * oh;
        float iou = i3 / fmaxf(a.vol + b.vol - i3, EPSF);
        // pack: higher iou wins; ties -> smaller column index (first argmax)
        unsigned long long pack =
            ((unsigned long long)__float_as_uint(iou) << 32) |
            (unsigned long long)(0xFFFFFFFFu - (unsigned)j);
        atomicMax(&g_rowbest[i], pack);
    }
}

__global__ void k_final(float* __restrict__ out) {
    int t = blockIdx.x * blockDim.x + threadIdx.x;
    if (t >= NBOX) return;
    unsigned long long b = g_rowbest[t];
    float v = __uint_as_float((unsigned)(b >> 32));
    unsigned idx = 0xFFFFFFFFu - (unsigned)(b & 0xFFFFFFFFull);
    float mo = (v > 0.75f) ? 1.0f : ((v < 0.25f) ? 0.0f : v);
    out[2 * NBOX + t] = mo;
    out[3 * NBOX + t] = (float)idx;
}

// ---------------------------------------------------------------------------
extern "C" void kernel_launch(void* const* d_in, const int* in_sizes, int n_in,
                              void* d_out, int out_size) {
    const float* labels = (const float*)d_in[0];
    const float* pred   = (const float*)d_in[1];
    const float* gt     = (const float*)d_in[2];
    const float* cls    = (const float*)d_in[3];
    // defensively resolve the 7-wide / 8-wide box tensors by element count
    for (int i = 0; i < n_in; i++) {
        if (in_sizes[i] == NBOX * 7) pred = (const float*)d_in[i];
        else if (in_sizes[i] == NBOX * 8) gt = (const float*)d_in[i];
    }
    float* out = (float*)d_out;

    k_init<<<(NBOX * 32 + 255) / 256, 256>>>(labels, cls, out);
    k_prep<<<8, 256>>>(pred, gt);
    k_sort<<<1, NBOX>>>(labels);
    dim3 gp(4, NBOX);
    k_prune_gg<<<gp, 256>>>();
    k_heavy_gg<<<296, 128>>>();
    k_nms<<<1, 32>>>();
    k_prune_pg<<<gp, 256>>>();
    k_heavy_pg<<<296, 128>>>();
    k_final<<<4, 256>>>(out);
}

// round 3
// speedup vs baseline: 1.0426x; 1.0426x over previous
#include <cuda_runtime.h>
#include <math.h>

#define NBOX 1024
#define EPSF 1e-8f
#define NMS_TH 0.1f
#define MAXP (1<<18)
#define GRID 148
#define TPB 256
#define NTH (GRID*TPB)

struct Box {
    float cx, cy, hx, hy, cs, sn;
    float corx[4], cory[4];
    float rad, zmin, zmax, area, vol;
    float pad;
};

__device__ Box g_gt[NBOX];
__device__ Box g_pred[NBOX];
__device__ float4 g_qgt[NBOX];     // cx, cy, rad, zmin
__device__ float4 g_qpred[NBOX];   // cx, cy, rad, zmin
__device__ float g_zmaxgt[NBOX];
__device__ float g_zmaxpred[NBOX];
__device__ unsigned g_supp[NBOX * 32];      // suppression bitmask, sorted-order rows
__device__ int g_order[NBOX];               // sorted pos -> orig idx
__device__ int g_pos[NBOX];                 // orig idx -> sorted pos
__device__ int g_keep_orig[NBOX];           // keep flag per orig gt idx
__device__ int g_cnt_gg;
__device__ int g_cnt_pg;
__device__ unsigned g_pairs_gg[MAXP];
__device__ unsigned g_pairs_pg[MAXP];
__device__ float g_ioupg[MAXP];
__device__ unsigned long long g_rowbest[NBOX];

// persistent-grid barrier state (monotonic; survives graph replays)
__device__ unsigned g_bar_arrive;
__device__ volatile unsigned g_bar_release;

__device__ __forceinline__ void gbar() {
    __syncthreads();
    if (threadIdx.x == 0) {
        __threadfence();
        unsigned t = atomicAdd(&g_bar_arrive, 1u) + 1u;
        unsigned need = ((t + GRID - 1u) / GRID) * GRID;
        if (t == need) {
            g_bar_release = need;
        } else {
            while (g_bar_release < need) { __nanosleep(32); }
        }
        __threadfence();
    }
    __syncthreads();
}

// ---------------------------------------------------------------------------
// Rotated-rectangle intersection area — identical math to the passing R1 code.
// ---------------------------------------------------------------------------
__device__ float inter_area(const Box& a, const Box& b) {
    float px[24], py[24];
    int k = 0;

#pragma unroll
    for (int q = 0; q < 4; q++) {
        float dxp = a.corx[q] - b.cx, dyp = a.cory[q] - b.cy;
        float lx =  dxp * b.cs + dyp * b.sn;
        float ly = -dxp * b.sn + dyp * b.cs;
        if (fabsf(lx) <= b.hx + 1e-5f && fabsf(ly) <= b.hy + 1e-5f) {
            px[k] = a.corx[q]; py[k] = a.cory[q]; k++;
        }
    }
#pragma unroll
    for (int q = 0; q < 4; q++) {
        float dxp = b.corx[q] - a.cx, dyp = b.cory[q] - a.cy;
        float lx =  dxp * a.cs + dyp * a.sn;
        float ly = -dxp * a.sn + dyp * a.cs;
        if (fabsf(lx) <= a.hx + 1e-5f && fabsf(ly) <= a.hy + 1e-5f) {
            px[k] = b.corx[q]; py[k] = b.cory[q]; k++;
        }
    }
#pragma unroll
    for (int p = 0; p < 4; p++) {
        float a0x = a.corx[p], a0y = a.cory[p];
        float a1x = a.corx[(p + 1) & 3], a1y = a.cory[(p + 1) & 3];
        float d1x = a1x - a0x, d1y = a1y - a0y;
#pragma unroll
        for (int q = 0; q < 4; q++) {
            float b0x = b.corx[q], b0y = b.cory[q];
            float b1x = b.corx[(q + 1) & 3], b1y = b.cory[(q + 1) & 3];
            float d2x = b1x - b0x, d2y = b1y - b0y;
            float r0x = b0x - a0x, r0y = b0y - a0y;
            float den = d1x * d2y - d1y * d2x;
            if (fabsf(den) > EPSF) {
                float t = (r0x * d2y - r0y * d2x) / den;
                float u = (r0x * d1y - r0y * d1x) / den;
                if (t >= 0.f && t <= 1.f && u >= 0.f && u <= 1.f) {
                    px[k] = a0x + t * d1x;
                    py[k] = a0y + t * d1y;
                    k++;
                }
            }
        }
    }

    if (k < 3) return 0.f;

    float sx = 0.f, sy = 0.f;
    for (int i = 0; i < k; i++) { sx += px[i]; sy += py[i]; }
    float fk = (float)k;
    float cxm = sx / fk, cym = sy / fk;

    float ang[24];
    for (int i = 0; i < k; i++) {
        px[i] -= cxm; py[i] -= cym;
        ang[i] = atan2f(py[i], px[i]);
    }
    for (int i = 1; i < k; i++) {
        float ax = px[i], ay = py[i], aa = ang[i];
        int j = i - 1;
        while (j >= 0 && ang[j] > aa) {
            px[j + 1] = px[j]; py[j + 1] = py[j]; ang[j + 1] = ang[j];
            j--;
        }
        px[j + 1] = ax; py[j + 1] = ay; ang[j + 1] = aa;
    }
    float s = 0.f;
    for (int i = 0; i < k; i++) {
        int j = (i + 1 == k) ? 0 : (i + 1);
        s += px[i] * py[j] - py[i] * px[j];
    }
    return 0.5f * fabsf(s);
}

// warp-aggregated pair emission
__device__ __forceinline__ void emit_pair(bool pass, unsigned code,
                                          int* cnt, unsigned* arr) {
    unsigned m = __ballot_sync(0xFFFFFFFFu, pass);
    if (!m) return;
    int lane = threadIdx.x & 31;
    int leader = __ffs(m) - 1;
    int base = 0;
    if (lane == leader) base = atomicAdd(cnt, __popc(m));
    base = __shfl_sync(0xFFFFFFFFu, base, leader);
    if (pass) {
        int idx = base + __popc(m & ((1u << lane) - 1u));
        if (idx < MAXP) arr[idx] = code;
    }
}

// ---------------------------------------------------------------------------
__global__ __launch_bounds__(TPB, 1)
void mega_kernel(const float* __restrict__ labels,
                 const float* __restrict__ pred_boxes,
                 const float* __restrict__ gt_boxes,
                 const float* __restrict__ cls,
                 float* __restrict__ out) {
    extern __shared__ unsigned s_mem[];   // 128KB: sort keys, then supp copy
    const int tid = threadIdx.x;
    const int bid = blockIdx.x;
    const int gtid = bid * TPB + tid;

    // ================= Phase A: init + per-box precompute ==================
    for (int t = gtid; t < NBOX * 32; t += NTH) g_supp[t] = 0u;
    if (gtid == 0) { g_cnt_gg = 0; g_cnt_pg = 0; }
    if (gtid < NBOX) {
        g_rowbest[gtid] = 0xFFFFFFFFull;   // (iou=0)<<32 | ~0 (idx 0)
        float lab = labels[gtid];
        float sgm = 1.0f / (1.0f + expf(-cls[gtid]));
        out[gtid] = (sgm > 0.55f && lab > 0.55f) ? 1.0f : 0.0f;
        out[NBOX + gtid] = lab;
    }
    for (int t = gtid; t < 2 * NBOX; t += NTH) {
        bool isgt = (t < NBOX);
        int i = isgt ? t : t - NBOX;
        const float* p = isgt ? (gt_boxes + i * 8) : (pred_boxes + i * 7);
        Box b;
        b.cx = p[0]; b.cy = p[1];
        float z = p[2], dx = p[3], dy = p[4], dz = p[5], r = p[6];
        b.hx = 0.5f * dx; b.hy = 0.5f * dy;
        float csn = cosf(r), snn = sinf(r);
        b.cs = csn; b.sn = snn;
        const float sxt[4] = {1.f, 1.f, -1.f, -1.f};
        const float syt[4] = {1.f, -1.f, -1.f, 1.f};
#pragma unroll
        for (int q = 0; q < 4; q++) {
            float lx = sxt[q] * b.hx, ly = syt[q] * b.hy;
            b.corx[q] = lx * csn - ly * snn + b.cx;
            b.cory[q] = lx * snn + ly * csn + b.cy;
        }
        b.rad = sqrtf(b.hx * b.hx + b.hy * b.hy) + 5e-4f;
        b.zmin = z - dz * 0.5f;
        b.zmax = z + dz * 0.5f;
        b.area = dx * dy;
        b.vol = dx * dy * dz;
        b.pad = 0.f;
        if (isgt) {
            g_gt[i] = b;
            g_qgt[i] = make_float4(b.cx, b.cy, b.rad, b.zmin);
            g_zmaxgt[i] = b.zmax;
        } else {
            g_pred[i] = b;
            g_qpred[i] = make_float4(b.cx, b.cy, b.rad, b.zmin);
            g_zmaxpred[i] = b.zmax;
        }
    }
    gbar();

    // ============ Phase B: sort (block 0) || prune gg+pg (others) ==========
    if (bid == 0) {
        unsigned long long* key = (unsigned long long*)s_mem;
        for (int t = tid; t < NBOX; t += TPB) {
            unsigned u = __float_as_uint(labels[t]);
            u = (u & 0x80000000u) ? ~u : (u | 0x80000000u);
            key[t] = ((unsigned long long)(~u) << 32) | (unsigned)t;
        }
        __syncthreads();
        for (int k2 = 2; k2 <= NBOX; k2 <<= 1) {
            for (int j = k2 >> 1; j > 0; j >>= 1) {
                for (int t = tid; t < NBOX; t += TPB) {
                    int ixj = t ^ j;
                    if (ixj > t) {
                        unsigned long long A = key[t], B = key[ixj];
                        bool up = ((t & k2) == 0);
                        if ((A > B) == up) { key[t] = B; key[ixj] = A; }
                    }
                }
                __syncthreads();
            }
        }
        for (int t = tid; t < NBOX; t += TPB) {
            int orig = (int)(unsigned)(key[t] & 0xFFFFFFFFull);
            g_order[t] = orig;
            g_pos[orig] = t;
        }
    } else {
        const int NW = (GRID - 1) * (TPB / 32);
        int gw = (bid - 1) * (TPB / 32) + (tid >> 5);
        int lane = tid & 31;
        for (int row = gw; row < 2 * NBOX; row += NW) {
            if (row < NBOX) {          // gt x gt, upper triangle
                float4 qi = g_qgt[row];
                for (int jj = lane; jj < NBOX; jj += 32) {
                    bool pass = false;
                    if (jj > row) {
                        float4 qj = g_qgt[jj];
                        float dx = qi.x - qj.x, dy = qi.y - qj.y;
                        float rr = qi.z + qj.z;
                        pass = (dx * dx + dy * dy <= rr * rr);
                    }
                    emit_pair(pass, ((unsigned)row << 10) | (unsigned)jj,
                              &g_cnt_gg, g_pairs_gg);
                }
            } else {                   // pred x gt (NO keep filter here)
                int i = row - NBOX;
                float4 qi = g_qpred[i];
                float zmaxi = g_zmaxpred[i];
                for (int jj = lane; jj < NBOX; jj += 32) {
                    float4 qj = g_qgt[jj];
                    float oh = fminf(zmaxi, g_zmaxgt[jj]) - fmaxf(qi.w, qj.w);
                    float dx = qi.x - qj.x, dy = qi.y - qj.y;
                    float rr = qi.z + qj.z;
                    bool pass = (oh > 0.f) && (dx * dx + dy * dy <= rr * rr);
                    emit_pair(pass, ((unsigned)i << 10) | (unsigned)jj,
                              &g_cnt_pg, g_pairs_pg);
                }
            }
        }
    }
    gbar();

    // ================= Phase C: heavy gt-gt IoU -> supp bits ===============
    {
        int n = g_cnt_gg; if (n > MAXP) n = MAXP;
        for (int idx = gtid; idx < n; idx += NTH) {
            unsigned pr = g_pairs_gg[idx];
            int i = pr >> 10, j = pr & 1023;
            float inter = inter_area(g_gt[i], g_gt[j]);
            float iou = inter / fmaxf(g_gt[i].area + g_gt[j].area - inter, EPSF);
            if (iou > NMS_TH) {
                int a = g_pos[i], b = g_pos[j];
                int lo = min(a, b), hi = max(a, b);
                atomicOr(&g_supp[lo * 32 + (hi >> 5)], 1u << (hi & 31));
            }
        }
    }
    gbar();

    // ====== Phase D: NMS scan (block 0) || heavy pred-gt IoU (others) ======
    if (bid == 0) {
        // cooperative copy of suppression matrix into shared
        for (int t = tid; t < NBOX * 32; t += TPB) s_mem[t] = g_supp[t];
        __syncthreads();
        if (tid < 32) {
            unsigned lane = tid;
            unsigned keep = 0xFFFFFFFFu;
            for (int w = 0; w < 32; w++) {
                unsigned kcur = __shfl_sync(0xFFFFFFFFu, keep, w);
                unsigned mrow[32], mdia[32];
#pragma unroll
                for (int u = 0; u < 32; u++) {
                    int i = w * 32 + u;
                    mrow[u] = s_mem[i * 32 + lane];
                    mdia[u] = s_mem[i * 32 + w];
                }
#pragma unroll
                for (int u = 0; u < 32; u++) {
                    if ((kcur >> u) & 1u) {
                        unsigned lowmask = (2u << u) - 1u;
                        unsigned m = mrow[u];
                        m = (lane < (unsigned)w) ? 0u
                            : ((lane == (unsigned)w) ? (m & ~lowmask) : m);
                        keep &= ~m;
                        kcur &= ~(mdia[u] & ~lowmask);
                    }
                }
            }
#pragma unroll
            for (int b = 0; b < 32; b++) {
                int a = (int)lane * 32 + b;
                int orig = g_order[a];
                g_keep_orig[orig] = (int)((keep >> b) & 1u);
            }
        }
    } else {
        int n = g_cnt_pg; if (n > MAXP) n = MAXP;
        const int NT2 = (GRID - 1) * TPB;
        int g2 = (bid - 1) * TPB + tid;
        for (int idx = g2; idx < n; idx += NT2) {
            unsigned pr = g_pairs_pg[idx];
            int i = pr >> 10, j = pr & 1023;
            const Box& a = g_pred[i];
            const Box& b = g_gt[j];
            float inter = inter_area(a, b);
            float oh = fmaxf(fminf(a.zmax, b.zmax) - fmaxf(a.zmin, b.zmin), 0.f);
            float i3 = inter * oh;
            g_ioupg[idx] = i3 / fmaxf(a.vol + b.vol - i3, EPSF);
        }
    }
    gbar();

    // ============ Phase E: keep-filtered per-row argmax reduction ==========
    {
        int n = g_cnt_pg; if (n > MAXP) n = MAXP;
        for (int idx = gtid; idx < n; idx += NTH) {
            unsigned pr = g_pairs_pg[idx];
            int i = pr >> 10, j = pr & 1023;
            if (g_keep_orig[j]) {
                unsigned long long pack =
                    ((unsigned long long)__float_as_uint(g_ioupg[idx]) << 32) |
                    (unsigned long long)(0xFFFFFFFFu - (unsigned)j);
                atomicMax(&g_rowbest[i], pack);
            }
        }
    }
    gbar();

    // ======================= Phase F: finalize output ======================
    if (gtid < NBOX) {
        unsigned long long b = g_rowbest[gtid];
        float v = __uint_as_float((unsigned)(b >> 32));
        unsigned idx = 0xFFFFFFFFu - (unsigned)(b & 0xFFFFFFFFull);
        float mo = (v > 0.75f) ? 1.0f : ((v < 0.25f) ? 0.0f : v);
        out[2 * NBOX + gtid] = mo;
        out[3 * NBOX + gtid] = (float)idx;
    }
}

// ---------------------------------------------------------------------------
extern "C" void kernel_launch(void* const* d_in, const int* in_sizes, int n_in,
                              void* d_out, int out_size) {
    const float* labels = (const float*)d_in[0];
    const float* pred   = (const float*)d_in[1];
    const float* gt     = (const float*)d_in[2];
    const float* cls    = (const float*)d_in[3];
    for (int i = 0; i < n_in; i++) {
        if (in_sizes[i] == NBOX * 7) pred = (const float*)d_in[i];
        else if (in_sizes[i] == NBOX * 8) gt = (const float*)d_in[i];
    }
    float* out = (float*)d_out;

    static int smem_set = 0;
    if (!smem_set) {
        cudaFuncSetAttribute(mega_kernel,
                             cudaFuncAttributeMaxDynamicSharedMemorySize,
                             131072);
        smem_set = 1;
    }
    mega_kernel<<<GRID, TPB, 131072>>>(labels, pred, gt, cls, out);
}